// round 4
// baseline (speedup 1.0000x reference)
#include <cuda_runtime.h>
#include <math.h>

#define NB 16384
#define NM 50
#define ND 64
#define WPB 4   // independent warps per CTA (each owns its own rows)

__device__ unsigned g_next;

__global__ void reset_counter() { g_next = 0; }

#define FULLM 0xffffffffu
#define FMA2(d,a,b,c)  asm("fma.rn.f32x2 %0, %1, %2, %3;" : "=l"(d) : "l"(a), "l"(b), "l"(c))
#define PACK2(d,lo,hi) asm("mov.b64 %0, {%1, %2};" : "=l"(d) : "f"(lo), "f"(hi))
#define UNPACK2(lo,hi,s) asm("mov.b64 {%0, %1}, %2;" : "=f"(lo), "=f"(hi) : "l"(s))

__global__ __launch_bounds__(32 * WPB, 7)
void agree_kernel(
    const int* __restrict__ group_inputs,
    const int* __restrict__ item_inputs,
    const int* __restrict__ member_ids,
    const int* __restrict__ member_lengths,
    const float* __restrict__ user_table,
    const float* __restrict__ item_table,
    const float* __restrict__ group_table,
    const float* __restrict__ att_w1,
    const float* __restrict__ att_b1,
    const float* __restrict__ att_w2,
    const float* __restrict__ att_b2,
    const float* __restrict__ pred_w1,
    const float* __restrict__ pred_b1,
    const float* __restrict__ pred_w2,
    const float* __restrict__ pred_b2,
    float* __restrict__ out)
{
    // member pair staging, double buffered. One member = 72 words:
    // d[0..31] at 0..31, d[32..63] at 36..67 (pad kills bank aliasing).
    __shared__ __align__(16) float s_me[WPB][2][2][72];
    __shared__ __align__(16) float s_new[WPB][3 * ND];  // [elem | g | item_e]

    const int warp = threadIdx.x >> 5;
    const int lane = threadIdx.x & 31;
    const int c0 = lane & 15;   // att hidden unit this lane owns
    const int h  = lane >> 4;   // d-half this lane owns

    float* const s_item = &s_new[warp][2 * ND];
    float* const meb    = &s_me[warp][0][0][0];       // buf stride 144 words
    const int stoff = 4 * c0 + ((c0 >= 8) ? 4 : 0);   // padded store offset

    // ---- warp-lifetime constants: W1a slice packed as f32x2 pairs ----
    unsigned long long wcp[16];
    #pragma unroll
    for (int k = 0; k < 16; k++) {
        float lo = att_w1[(h * 32 + 2 * k)     * 16 + c0];
        float hi = att_w1[(h * 32 + 2 * k + 1) * 16 + c0];
        PACK2(wcp[k], lo, hi);
    }
    const float w2c = att_w2[c0];
    const float b2  = att_b2[0];

    // ---- dynamic work-stealing over rows ----
    int row = 0;
    if (lane == 0) row = (int)atomicAdd(&g_next, 1u);
    row = __shfl_sync(FULLM, row, 0);

    while (row < NB) {
        int nxt = 0;
        if (lane == 0) nxt = (int)atomicAdd(&g_next, 1u);  // latency hidden by row work

        // ---- row prologue: item embedding, ids, lengths ----
        const int len = member_lengths[row];          // member m valid iff m <= len
        const int npairs = (len >> 1) + 1;
        {
            const float* itrow = item_table + (size_t)item_inputs[row] * ND;
            s_item[lane]      = itrow[lane];
            s_item[lane + 32] = itrow[lane + 32];
        }
        const int idsA = member_ids[row * NM + lane];
        const int idsB = (lane < NM - 32) ? member_ids[row * NM + 32 + lane] : 0;
        __syncwarp();

        // prefetch pair 0 (half h loads member h's row, float4 per lane)
        float4 r;
        {
            int mid = __shfl_sync(FULLM, idsA, h);
            r = ((const float4*)(user_table + (size_t)mid * ND))[c0];
        }

        // cconst[c0] = b1 + item_e @ W1b, split per d-half + combine
        float cc = 0.f;
        {
            const float4* si4 = (const float4*)(s_item + h * 32);
            #pragma unroll
            for (int dd = 0; dd < 8; dd++) {
                float4 v = si4[dd];
                int db = (ND + h * 32 + 4 * dd) * 16 + c0;
                cc = fmaf(v.x, att_w1[db],      cc);
                cc = fmaf(v.y, att_w1[db + 16], cc);
                cc = fmaf(v.z, att_w1[db + 32], cc);
                cc = fmaf(v.w, att_w1[db + 48], cc);
            }
        }
        const float cconst = cc + __shfl_xor_sync(FULLM, cc, 16) + att_b1[c0];

        // plain-exp softmax (scores are O(0.3) by construction — no max shift)
        float denom = 0.f, g0 = 0.f, g1 = 0.f;

        #pragma unroll 1
        for (int p = 0; p < npairs; p++) {
            float* mb = meb + (p & 1) * 144;

            *(float4*)(mb + h * 72 + stoff) = r;   // stage pair p
            __syncwarp();

            if (p + 1 < npairs) {                  // prefetch pair p+1
                int m = 2 * (p + 1) + h;
                int mid = __shfl_sync(FULLM, (m < 32) ? idsA : idsB, m & 31);
                r = ((const float4*)(user_table + (size_t)mid * ND))[c0];
            }

            // packed dots over this lane's 32-d slice, both members
            const ulonglong2* q0 = (const ulonglong2*)(mb + h * 36);
            const ulonglong2* q1 = (const ulonglong2*)(mb + 72 + h * 36);
            unsigned long long a0 = 0ull, a1 = 0ull, b0 = 0ull, b1v = 0ull;
            #pragma unroll
            for (int i = 0; i < 8; i++) {
                ulonglong2 m0 = q0[i];
                FMA2(a0, m0.x, wcp[2 * i],     a0);
                FMA2(a1, m0.y, wcp[2 * i + 1], a1);
                ulonglong2 m1 = q1[i];
                FMA2(b0, m1.x, wcp[2 * i],     b0);
                FMA2(b1v, m1.y, wcp[2 * i + 1], b1v);
            }
            float x0, x1, y0, y1, z0, z1, u0, u1;
            UNPACK2(x0, x1, a0); UNPACK2(y0, y1, a1);
            UNPACK2(z0, z1, b0); UNPACK2(u0, u1, b1v);
            float p0 = (x0 + x1) + (y0 + y1);
            float p1 = (z0 + z1) + (u0 + u1);

            // combine d-halves, relu/score, reduce over 16 columns
            float A0 = p0 + __shfl_xor_sync(FULLM, p0, 16);
            float A1 = p1 + __shfl_xor_sync(FULLM, p1, 16);
            float t0 = fmaxf(A0 + cconst, 0.f) * w2c;
            float t1 = fmaxf(A1 + cconst, 0.f) * w2c;
            #pragma unroll
            for (int dlt = 1; dlt < 16; dlt <<= 1) {
                t0 += __shfl_xor_sync(FULLM, t0, dlt);
                t1 += __shfl_xor_sync(FULLM, t1, dlt);
            }
            bool  v1 = (2 * p + 1 <= len);
            float e0 = __expf(t0 + b2);
            float e1 = v1 ? __expf(t1 + b2) : 0.f;
            denom += e0 + e1;

            float m0a = mb[lane];            // member0 dim lane
            float m0b = mb[lane + 36];       // member0 dim lane+32
            float m1a = mb[72 + lane];       // member1 dim lane
            float m1b = mb[72 + 36 + lane];  // member1 dim lane+32
            g0 = fmaf(e0, m0a, fmaf(e1, m1a, g0));
            g1 = fmaf(e0, m0b, fmaf(e1, m1b, g1));
        }

        // ---- g = softmax-pooled members + group embedding ----
        const float inv = 1.0f / denom;
        const size_t gid = (size_t)group_inputs[row];
        float gg0 = fmaf(g0, inv, group_table[gid * ND + lane]);
        float gg1 = fmaf(g1, inv, group_table[gid * ND + lane + 32]);

        float it0 = s_item[lane], it1 = s_item[lane + 32];
        s_new[warp][lane]           = gg0 * it0;   // elem
        s_new[warp][lane + 32]      = gg1 * it1;
        s_new[warp][ND + lane]      = gg0;         // g
        s_new[warp][ND + lane + 32] = gg1;
        __syncwarp();

        // ---- predict MLP: new_e[192] -> 8 -> 1 -> sigmoid ----
        const int j = lane & 7;        // hidden unit
        const int q = lane >> 3;       // k-quarter (48 elems each)
        float ph = 0.f;
        #pragma unroll 12
        for (int i = 0; i < 48; i++) {
            int k = q * 48 + i;
            ph = fmaf(s_new[warp][k], pred_w1[k * 8 + j], ph);
        }
        ph += __shfl_xor_sync(FULLM, ph, 8);
        ph += __shfl_xor_sync(FULLM, ph, 16);

        float hj = fmaxf(ph + pred_b1[j], 0.f);
        float t2 = hj * pred_w2[j];
        t2 += __shfl_xor_sync(FULLM, t2, 1);
        t2 += __shfl_xor_sync(FULLM, t2, 2);
        t2 += __shfl_xor_sync(FULLM, t2, 4);

        if (lane == 0) {
            float z = t2 + pred_b2[0];
            out[row] = 1.0f / (1.0f + __expf(-z));
        }

        nxt = __shfl_sync(FULLM, nxt, 0);
        row = nxt;
        __syncwarp();   // protect s_new/s_me reuse across rows
    }
}

extern "C" void kernel_launch(void* const* d_in, const int* in_sizes, int n_in,
                              void* d_out, int out_size) {
    (void)in_sizes; (void)n_in; (void)out_size;
    reset_counter<<<1, 1>>>();
    agree_kernel<<<148 * 7, 32 * WPB>>>(
        (const int*)d_in[0],   // group_inputs
        (const int*)d_in[1],   // item_inputs
        (const int*)d_in[2],   // member_ids
        (const int*)d_in[3],   // member_lengths
        (const float*)d_in[4], // user_table
        (const float*)d_in[5], // item_table
        (const float*)d_in[6], // group_table
        (const float*)d_in[7], // att_w1
        (const float*)d_in[8], // att_b1
        (const float*)d_in[9], // att_w2
        (const float*)d_in[10],// att_b2
        (const float*)d_in[11],// pred_w1
        (const float*)d_in[12],// pred_b1
        (const float*)d_in[13],// pred_w2
        (const float*)d_in[14],// pred_b2
        (float*)d_out);
}

// round 5
// speedup vs baseline: 1.1138x; 1.1138x over previous
#include <cuda_runtime.h>
#include <math.h>

#define NB 16384
#define NM 50
#define ND 64

#define FULLM 0xffffffffu

__global__ __launch_bounds__(32, 32)
void agree_kernel(
    const int* __restrict__ group_inputs,
    const int* __restrict__ item_inputs,
    const int* __restrict__ member_ids,
    const int* __restrict__ member_lengths,
    const float* __restrict__ user_table,
    const float* __restrict__ item_table,
    const float* __restrict__ group_table,
    const float* __restrict__ att_w1,
    const float* __restrict__ att_b1,
    const float* __restrict__ att_w2,
    const float* __restrict__ att_b2,
    const float* __restrict__ pred_w1,
    const float* __restrict__ pred_b1,
    const float* __restrict__ pred_w2,
    const float* __restrict__ pred_b2,
    float* __restrict__ out)
{
    // member pair staging, double buffered. One member = 72 words:
    // d[0..31] at 0..31, d[32..63] at 36..67 (pad kills bank aliasing).
    __shared__ __align__(16) float s_me[2][2][72];
    __shared__ __align__(16) float s_new[3 * ND];  // [elem | g | item_e]

    const int lane = threadIdx.x & 31;
    const int b = blockIdx.x;

    const int c0 = lane & 15;   // att hidden unit this lane owns
    const int h  = lane >> 4;   // d-half AND "own member" of this lane

    float* s_item = &s_new[2 * ND];

    // ---- item embedding into smem ----
    {
        const float* itrow = item_table + (size_t)item_inputs[b] * ND;
        s_item[lane]      = itrow[lane];
        s_item[lane + 32] = itrow[lane + 32];
    }
    __syncwarp();

    // ---- all member ids into registers ----
    const int idsA = member_ids[b * NM + lane];
    const int idsB = (lane < NM - 32) ? member_ids[b * NM + 32 + lane] : 0;

    // ---- W1a slice: column c0, d-range [h*32, h*32+32)  (32 regs) ----
    float wc[32];
    #pragma unroll
    for (int k = 0; k < 32; k++) wc[k] = att_w1[(h * 32 + k) * 16 + c0];

    // ---- cconst[c0] = att_b1 + item_e @ W1b (per-batch constant) ----
    float cconst = att_b1[c0];
    #pragma unroll 8
    for (int d = 0; d < ND; d++)
        cconst = fmaf(s_item[d], att_w1[(ND + d) * 16 + c0], cconst);

    const float w2c = att_w2[c0];
    const float b2  = att_b2[0];
    const int  len  = member_lengths[b];     // member m valid iff m <= len
    const int  npairs = (len >> 1) + 1;

    // plain-exp softmax (scores are O(0.3) by construction — no max shift)
    float denom = 0.f, g0 = 0.f, g1 = 0.f;

    // ---- preload pair 0 (half h loads member h's row, float4 per lane) ----
    float4 r;
    {
        int mid = __shfl_sync(FULLM, idsA, h);
        r = ((const float4*)(user_table + (size_t)mid * ND))[c0];
    }

    float* const meb = &s_me[0][0][0];               // buf stride 144 words
    const int stoff = 4 * c0 + ((c0 >= 8) ? 4 : 0);  // padded store offset

    #pragma unroll 1
    for (int p = 0; p < npairs; p++) {
        float* mb = meb + (p & 1) * 144;

        // stage pair p
        *(float4*)(mb + h * 72 + stoff) = r;
        __syncwarp();

        // prefetch pair p+1 (latency covered by this pair's compute)
        if (p + 1 < npairs) {
            int m = 2 * (p + 1) + h;
            int mid = __shfl_sync(FULLM, (m < 32) ? idsA : idsB, m & 31);
            r = ((const float4*)(user_table + (size_t)mid * ND))[c0];
        }

        // partial dots over this lane's 32-d slice, both members,
        // 2 accumulators per member to halve FMA chain depth
        const float4* me0 = (const float4*)(mb + h * 36);
        const float4* me1 = (const float4*)(mb + 72 + h * 36);
        float p0a = 0.f, p0b = 0.f, p1a = 0.f, p1b = 0.f;
        #pragma unroll
        for (int i = 0; i < 8; i += 2) {
            float4 a = me0[i];
            p0a = fmaf(a.x, wc[4 * i + 0], p0a);
            p0a = fmaf(a.y, wc[4 * i + 1], p0a);
            p0a = fmaf(a.z, wc[4 * i + 2], p0a);
            p0a = fmaf(a.w, wc[4 * i + 3], p0a);
            float4 a2 = me0[i + 1];
            p0b = fmaf(a2.x, wc[4 * i + 4], p0b);
            p0b = fmaf(a2.y, wc[4 * i + 5], p0b);
            p0b = fmaf(a2.z, wc[4 * i + 6], p0b);
            p0b = fmaf(a2.w, wc[4 * i + 7], p0b);
            float4 e = me1[i];
            p1a = fmaf(e.x, wc[4 * i + 0], p1a);
            p1a = fmaf(e.y, wc[4 * i + 1], p1a);
            p1a = fmaf(e.z, wc[4 * i + 2], p1a);
            p1a = fmaf(e.w, wc[4 * i + 3], p1a);
            float4 e2 = me1[i + 1];
            p1b = fmaf(e2.x, wc[4 * i + 4], p1b);
            p1b = fmaf(e2.y, wc[4 * i + 5], p1b);
            p1b = fmaf(e2.z, wc[4 * i + 6], p1b);
            p1b = fmaf(e2.w, wc[4 * i + 7], p1b);
        }
        float p0 = p0a + p0b;   // member0, this lane's d-half
        float p1 = p1a + p1b;   // member1, this lane's d-half

        // own-member assembly: lane (c0,h) gets full column-c0 dot of member h.
        // u = own member's partial (d-half h); v = other member's partial;
        // peer lane (c0,1-h) sends its v = own member's other d-half.
        float u = h ? p1 : p0;
        float v = h ? p0 : p1;
        float A = u + __shfl_xor_sync(FULLM, v, 16);
        float t = fmaxf(A + cconst, 0.f) * w2c;

        // butterfly over the 16 columns within each half (halves disjoint:
        // half0 reduces member0's score, half1 member1's — in parallel)
        t += __shfl_xor_sync(FULLM, t, 1);
        t += __shfl_xor_sync(FULLM, t, 2);
        t += __shfl_xor_sync(FULLM, t, 4);
        t += __shfl_xor_sync(FULLM, t, 8);

        // one exp per lane (both members' exps run concurrently)
        bool valid = (2 * p + h <= len);       // h=0 always valid in-loop
        float e = valid ? __expf(t + b2) : 0.f;

        // broadcast both members' weights to all lanes
        float e0 = __shfl_sync(FULLM, e, 0);
        float e1 = __shfl_sync(FULLM, e, 16);
        denom += e0 + e1;

        float m0a = mb[lane];            // member0 dim lane
        float m0b = mb[lane + 36];       // member0 dim lane+32
        float m1a = mb[72 + lane];       // member1 dim lane
        float m1b = mb[72 + 36 + lane];  // member1 dim lane+32
        g0 = fmaf(e0, m0a, fmaf(e1, m1a, g0));
        g1 = fmaf(e0, m0b, fmaf(e1, m1b, g1));
        // no trailing sync: next iteration writes the other buffer
    }

    // ---- g = softmax-pooled members + group embedding ----
    const float inv = 1.0f / denom;
    const size_t gid = (size_t)group_inputs[b];
    float gg0 = fmaf(g0, inv, group_table[gid * ND + lane]);
    float gg1 = fmaf(g1, inv, group_table[gid * ND + lane + 32]);

    float it0 = s_item[lane], it1 = s_item[lane + 32];
    s_new[lane]           = gg0 * it0;   // elem
    s_new[lane + 32]      = gg1 * it1;
    s_new[ND + lane]      = gg0;         // g
    s_new[ND + lane + 32] = gg1;
    __syncwarp();

    // ---- predict MLP: new_e[192] -> 8 -> 1 -> sigmoid ----
    const int j = lane & 7;        // hidden unit
    const int q = lane >> 3;       // k-quarter (48 elems each)
    float ph = 0.f;
    #pragma unroll 12
    for (int i = 0; i < 48; i++) {
        int k = q * 48 + i;
        ph = fmaf(s_new[k], pred_w1[k * 8 + j], ph);
    }
    ph += __shfl_xor_sync(FULLM, ph, 8);
    ph += __shfl_xor_sync(FULLM, ph, 16);

    float hj = fmaxf(ph + pred_b1[j], 0.f);
    float t2 = hj * pred_w2[j];
    t2 += __shfl_xor_sync(FULLM, t2, 1);
    t2 += __shfl_xor_sync(FULLM, t2, 2);
    t2 += __shfl_xor_sync(FULLM, t2, 4);

    if (lane == 0) {
        float z = t2 + pred_b2[0];
        out[b] = 1.0f / (1.0f + __expf(-z));
    }
}

extern "C" void kernel_launch(void* const* d_in, const int* in_sizes, int n_in,
                              void* d_out, int out_size) {
    (void)in_sizes; (void)n_in; (void)out_size;
    agree_kernel<<<NB, 32>>>(
        (const int*)d_in[0],   // group_inputs
        (const int*)d_in[1],   // item_inputs
        (const int*)d_in[2],   // member_ids
        (const int*)d_in[3],   // member_lengths
        (const float*)d_in[4], // user_table
        (const float*)d_in[5], // item_table
        (const float*)d_in[6], // group_table
        (const float*)d_in[7], // att_w1
        (const float*)d_in[8], // att_b1
        (const float*)d_in[9], // att_w2
        (const float*)d_in[10],// att_b2
        (const float*)d_in[11],// pred_w1
        (const float*)d_in[12],// pred_b1
        (const float*)d_in[13],// pred_w2
        (const float*)d_in[14],// pred_b2
        (float*)d_out);
}

// round 6
// speedup vs baseline: 1.1324x; 1.0167x over previous
#include <cuda_runtime.h>
#include <math.h>

#define NB 16384
#define NM 50
#define ND 64

#define FULLM 0xffffffffu

__global__ __launch_bounds__(32, 28)
void agree_kernel(
    const int* __restrict__ group_inputs,
    const int* __restrict__ item_inputs,
    const int* __restrict__ member_ids,
    const int* __restrict__ member_lengths,
    const float* __restrict__ user_table,
    const float* __restrict__ item_table,
    const float* __restrict__ group_table,
    const float* __restrict__ att_w1,
    const float* __restrict__ att_b1,
    const float* __restrict__ att_w2,
    const float* __restrict__ att_b2,
    const float* __restrict__ pred_w1,
    const float* __restrict__ pred_b1,
    const float* __restrict__ pred_w2,
    const float* __restrict__ pred_b2,
    float* __restrict__ out)
{
    // member pair staging, double buffered. One member = 72 words:
    // d[0..31] at 0..31, d[32..63] at 36..67 (pad kills bank aliasing).
    __shared__ __align__(16) float s_me[2][2][72];
    __shared__ __align__(16) float s_new[3 * ND];  // [elem | g | item_e]

    const int lane = threadIdx.x & 31;
    const int b = blockIdx.x;

    const int c0 = lane & 15;   // att hidden unit / float4-chunk this lane owns
    const int h  = lane >> 4;   // d-half AND "own member" of this lane

    float* s_item = &s_new[2 * ND];

    // ---- item embedding into smem ----
    {
        const float* itrow = item_table + (size_t)item_inputs[b] * ND;
        s_item[lane]      = itrow[lane];
        s_item[lane + 32] = itrow[lane + 32];
    }
    __syncwarp();

    // ---- all member ids into registers ----
    const int idsA = member_ids[b * NM + lane];
    const int idsB = (lane < NM - 32) ? member_ids[b * NM + 32 + lane] : 0;

    // ---- W1a slice: column c0, d-range [h*32, h*32+32)  (32 regs) ----
    float wc[32];
    #pragma unroll
    for (int k = 0; k < 32; k++) wc[k] = att_w1[(h * 32 + k) * 16 + c0];

    // ---- cconst[c0] = att_b1 + item_e @ W1b, split per d-half + combine ----
    float cconst;
    {
        float cc = 0.f;
        const float4* si4 = (const float4*)(s_item + h * 32);
        #pragma unroll
        for (int dd = 0; dd < 8; dd++) {
            float4 v = si4[dd];
            int db = (ND + h * 32 + 4 * dd) * 16 + c0;
            cc = fmaf(v.x, att_w1[db],      cc);
            cc = fmaf(v.y, att_w1[db + 16], cc);
            cc = fmaf(v.z, att_w1[db + 32], cc);
            cc = fmaf(v.w, att_w1[db + 48], cc);
        }
        cconst = cc + __shfl_xor_sync(FULLM, cc, 16) + att_b1[c0];
    }

    const float w2c = att_w2[c0];
    const float b2  = att_b2[0];
    const int  len  = member_lengths[b];     // member m valid iff m <= len
    const int  npairs = (len >> 1) + 1;

    // plain-exp softmax (scores are O(0.3) by construction — no max shift).
    // Per-lane accumulators: gq = sum_p e_own(p) * mem_own[4c0..4c0+4),
    // dsum = sum_p e_own(p); cross-half combine after the loop.
    float dsum = 0.f;
    float4 gq = make_float4(0.f, 0.f, 0.f, 0.f);

    // ---- preload pair 0 (half h loads member h's row, float4 per lane) ----
    float4 r;
    {
        int mid = __shfl_sync(FULLM, idsA, h);
        r = ((const float4*)(user_table + (size_t)mid * ND))[c0];
    }

    float* const meb = &s_me[0][0][0];               // buf stride 144 words
    const int stoff = 4 * c0 + ((c0 >= 8) ? 4 : 0);  // padded store offset

    #pragma unroll 1
    for (int p = 0; p < npairs; p++) {
        float* mb = meb + (p & 1) * 144;

        // stage pair p; keep own-member chunk in regs for g-accumulation
        *(float4*)(mb + h * 72 + stoff) = r;
        float4 cur = r;
        __syncwarp();

        // prefetch pair p+1 (latency covered by this pair's compute)
        if (p + 1 < npairs) {
            int m = 2 * (p + 1) + h;
            int mid = __shfl_sync(FULLM, (m < 32) ? idsA : idsB, m & 31);
            r = ((const float4*)(user_table + (size_t)mid * ND))[c0];
        }

        // partial dots over this lane's 32-d slice, both members,
        // 2 accumulators per member to halve FMA chain depth
        const float4* me0 = (const float4*)(mb + h * 36);
        const float4* me1 = (const float4*)(mb + 72 + h * 36);
        float p0a = 0.f, p0b = 0.f, p1a = 0.f, p1b = 0.f;
        #pragma unroll
        for (int i = 0; i < 8; i += 2) {
            float4 a = me0[i];
            p0a = fmaf(a.x, wc[4 * i + 0], p0a);
            p0a = fmaf(a.y, wc[4 * i + 1], p0a);
            p0a = fmaf(a.z, wc[4 * i + 2], p0a);
            p0a = fmaf(a.w, wc[4 * i + 3], p0a);
            float4 a2 = me0[i + 1];
            p0b = fmaf(a2.x, wc[4 * i + 4], p0b);
            p0b = fmaf(a2.y, wc[4 * i + 5], p0b);
            p0b = fmaf(a2.z, wc[4 * i + 6], p0b);
            p0b = fmaf(a2.w, wc[4 * i + 7], p0b);
            float4 e = me1[i];
            p1a = fmaf(e.x, wc[4 * i + 0], p1a);
            p1a = fmaf(e.y, wc[4 * i + 1], p1a);
            p1a = fmaf(e.z, wc[4 * i + 2], p1a);
            p1a = fmaf(e.w, wc[4 * i + 3], p1a);
            float4 e2 = me1[i + 1];
            p1b = fmaf(e2.x, wc[4 * i + 4], p1b);
            p1b = fmaf(e2.y, wc[4 * i + 5], p1b);
            p1b = fmaf(e2.z, wc[4 * i + 6], p1b);
            p1b = fmaf(e2.w, wc[4 * i + 7], p1b);
        }
        float p0 = p0a + p0b;   // member0, this lane's d-half
        float p1 = p1a + p1b;   // member1, this lane's d-half

        // own-member assembly: lane (c0,h) gets full column-c0 dot of member h
        float u = h ? p1 : p0;
        float v = h ? p0 : p1;
        float A = u + __shfl_xor_sync(FULLM, v, 16);
        float t = fmaxf(A + cconst, 0.f) * w2c;

        // butterfly over the 16 columns within each half (halves disjoint:
        // half0 reduces member0's score, half1 member1's — in parallel).
        // Afterwards every lane of half h holds member-h's full score.
        t += __shfl_xor_sync(FULLM, t, 1);
        t += __shfl_xor_sync(FULLM, t, 2);
        t += __shfl_xor_sync(FULLM, t, 4);
        t += __shfl_xor_sync(FULLM, t, 8);

        // own-member weight; h=0 always valid in-loop
        float e = (2 * p + h <= len) ? __expf(t + b2) : 0.f;
        dsum += e;
        gq.x = fmaf(e, cur.x, gq.x);
        gq.y = fmaf(e, cur.y, gq.y);
        gq.z = fmaf(e, cur.z, gq.z);
        gq.w = fmaf(e, cur.w, gq.w);
        // no trailing sync: next iteration writes the other buffer
    }

    // ---- cross-half combine: full softmax-pooled g + group embedding ----
    gq.x += __shfl_xor_sync(FULLM, gq.x, 16);
    gq.y += __shfl_xor_sync(FULLM, gq.y, 16);
    gq.z += __shfl_xor_sync(FULLM, gq.z, 16);
    gq.w += __shfl_xor_sync(FULLM, gq.w, 16);
    dsum += __shfl_xor_sync(FULLM, dsum, 16);
    const float inv = 1.0f / dsum;

    const size_t gid = (size_t)group_inputs[b];
    float4 grp = ((const float4*)(group_table + gid * ND))[c0];
    float4 it4 = ((const float4*)s_item)[c0];

    float4 gg, el;
    gg.x = fmaf(gq.x, inv, grp.x);  el.x = gg.x * it4.x;
    gg.y = fmaf(gq.y, inv, grp.y);  el.y = gg.y * it4.y;
    gg.z = fmaf(gq.z, inv, grp.z);  el.z = gg.z * it4.z;
    gg.w = fmaf(gq.w, inv, grp.w);  el.w = gg.w * it4.w;

    // both halves hold identical values; duplicate same-data stores are benign
    ((float4*)&s_new[0])[c0]  = el;   // elem
    ((float4*)&s_new[ND])[c0] = gg;   // g
    __syncwarp();

    // ---- predict MLP: new_e[192] -> 8 -> 1 -> sigmoid ----
    const int j = lane & 7;        // hidden unit
    const int q = lane >> 3;       // k-quarter (48 elems each)
    float ph = 0.f;
    #pragma unroll 12
    for (int i = 0; i < 48; i++) {
        int k = q * 48 + i;
        ph = fmaf(s_new[k], pred_w1[k * 8 + j], ph);
    }
    ph += __shfl_xor_sync(FULLM, ph, 8);
    ph += __shfl_xor_sync(FULLM, ph, 16);

    float hj = fmaxf(ph + pred_b1[j], 0.f);
    float t2 = hj * pred_w2[j];
    t2 += __shfl_xor_sync(FULLM, t2, 1);
    t2 += __shfl_xor_sync(FULLM, t2, 2);
    t2 += __shfl_xor_sync(FULLM, t2, 4);

    if (lane == 0) {
        float z = t2 + pred_b2[0];
        out[b] = 1.0f / (1.0f + __expf(-z));
    }
}

extern "C" void kernel_launch(void* const* d_in, const int* in_sizes, int n_in,
                              void* d_out, int out_size) {
    (void)in_sizes; (void)n_in; (void)out_size;
    agree_kernel<<<NB, 32>>>(
        (const int*)d_in[0],   // group_inputs
        (const int*)d_in[1],   // item_inputs
        (const int*)d_in[2],   // member_ids
        (const int*)d_in[3],   // member_lengths
        (const float*)d_in[4], // user_table
        (const float*)d_in[5], // item_table
        (const float*)d_in[6], // group_table
        (const float*)d_in[7], // att_w1
        (const float*)d_in[8], // att_b1
        (const float*)d_in[9], // att_w2
        (const float*)d_in[10],// att_b2
        (const float*)d_in[11],// pred_w1
        (const float*)d_in[12],// pred_b1
        (const float*)d_in[13],// pred_w2
        (const float*)d_in[14],// pred_b2
        (float*)d_out);
}